// round 2
// baseline (speedup 1.0000x reference)
#include <cuda_runtime.h>
#include <cstdint>

// ================= problem constants =================
constexpr int B_ROWS = 65536;
constexpr int LDIM   = 1024;   // last_dim (GEMM1 N, GEMM2 K)
constexpr int COMB   = 1024;   // frame+esn (GEMM1 K)

// ================= tiling =================
constexpr int TM   = 128;            // batch rows per CTA
constexpr int N1C  = 128;            // GEMM1 N-chunk
constexpr int KB   = 32;             // K-chunk
constexpr int NN1  = LDIM / N1C;     // 8
constexpr int NKC  = COMB / KB;      // 32 GEMM1 k-chunks per n1
constexpr int NSC  = N1C / KB;       // 4  GEMM2 k-chunks per n1
constexpr int NIT  = NKC + NSC;      // 36 iterations per n1
constexpr int S_TOT = NN1 * NIT;     // 288

// ================= SMEM (floats) =================
constexpr int ABUF_F = TM * KB;      // 4096
constexpr int WBUF_F = N1C * KB;     // 4096
constexpr int Q_F    = TM * N1C;     // 16384
constexpr int SM_AB  = 0;
constexpr int SM_WB  = 2 * ABUF_F;         // 8192
constexpr int SM_Q   = SM_WB + 2 * WBUF_F; // 16384
constexpr int SMEM_BYTES = (SM_Q + Q_F) * 4;  // 131072

// fragment-ordered weights (tf32-rounded), built by prep kernel
__device__ __align__(16) float g_W1frag[NN1 * NKC * 4096];  // 4 MB
__device__ __align__(16) float g_W2frag[NN1 * NSC * 4096];  // 512 KB

// ================= helpers =================
__device__ __forceinline__ uint32_t smem_u32(const void* p) {
    uint32_t a;
    asm("{ .reg .u64 t; cvta.to.shared.u64 t, %1; cvt.u32.u64 %0, t; }" : "=r"(a) : "l"(p));
    return a;
}
__device__ __forceinline__ uint32_t f2tf32(float x) {  // round-to-nearest tf32
    uint32_t r;
    asm("cvt.rna.tf32.f32 %0, %1;" : "=r"(r) : "f"(x));
    return r;
}
__device__ __forceinline__ float fast_tanh(float x) {
    float r;
    asm("tanh.approx.f32 %0, %1;" : "=f"(r) : "f"(x));
    return r;
}
__device__ __forceinline__ void cp16(uint32_t saddr, const void* gptr) {
    asm volatile("cp.async.cg.shared.global [%0], [%1], 16;"
                 :: "r"(saddr), "l"((unsigned long long)__cvta_generic_to_global(gptr)) : "memory");
}
__device__ __forceinline__ void cp_commit() { asm volatile("cp.async.commit_group;" ::: "memory"); }
__device__ __forceinline__ void cp_wait0()  { asm volatile("cp.async.wait_group 0;"  ::: "memory"); }

__device__ __forceinline__ void mma8(float (&d)[4], const uint32_t (&a)[4], const uint32_t (&b)[2]) {
    asm volatile(
        "mma.sync.aligned.m16n8k8.row.col.f32.tf32.tf32.f32 "
        "{%0,%1,%2,%3},{%4,%5,%6,%7},{%8,%9},{%0,%1,%2,%3};"
        : "+f"(d[0]), "+f"(d[1]), "+f"(d[2]), "+f"(d[3])
        : "r"(a[0]), "r"(a[1]), "r"(a[2]), "r"(a[3]), "r"(b[0]), "r"(b[1]));
}

// one K=32 chunk of mma for this warp. abase: A-fragment layout
// [kk2][mt8][slot(32)][reg(4)]; wb: B-fragment layout [nt16][kk4][lane][reg2]
__device__ __forceinline__ void mma_chunk(const float* __restrict__ abase, int kkoff, bool axor,
                                          const float* __restrict__ wb,
                                          int wm, int wn, int lane, float (&acc)[2][8][4]) {
#pragma unroll
    for (int kk = 0; kk < 4; ++kk) {
        const int asl = axor ? (lane ^ kk) : lane;
        uint32_t af[2][4];
#pragma unroll
        for (int mt = 0; mt < 2; ++mt) {
            const float4 v = *reinterpret_cast<const float4*>(
                abase + ((((kkoff + kk) * 8 + wm * 2 + mt) * 32 + asl) << 2));
            af[mt][0] = __float_as_uint(v.x); af[mt][1] = __float_as_uint(v.y);
            af[mt][2] = __float_as_uint(v.z); af[mt][3] = __float_as_uint(v.w);
        }
        uint32_t bf[8][2];
#pragma unroll
        for (int nt = 0; nt < 8; ++nt) {
            const float2 v = *reinterpret_cast<const float2*>(
                wb + ((((wn * 8 + nt) * 4 + kk) * 32 + lane) << 1));
            bf[nt][0] = __float_as_uint(v.x); bf[nt][1] = __float_as_uint(v.y);
        }
#pragma unroll
        for (int mt = 0; mt < 2; ++mt)
#pragma unroll
            for (int nt = 0; nt < 8; ++nt) mma8(acc[mt][nt], af[mt], bf[nt]);
    }
}

// ================= prep: Toeplitz expand + frag shuffle + tf32 round =================
__global__ void prep_kernel(const float* __restrict__ W1,
                            const float* __restrict__ Wsl,
                            const float* __restrict__ Wint) {
    const int f = blockIdx.x * 256 + threadIdx.x;
    const int T1 = NN1 * NKC * 4096;
    if (f < T1) {
        const int blk = f >> 12, r = f & 4095;
        const int n1 = blk >> 5, kc = blk & 31;
        const int reg = r & 1, lane = (r >> 1) & 31, kk = (r >> 6) & 3, nt = (r >> 8) & 15;
        const int n = n1 * 128 + nt * 8 + (lane >> 2);
        const int k = kc * 32 + kk * 8 + reg * 4 + (lane & 3);
        const int t = 1023 - n + k;  // toeplitz param index
        const float v = (t < 1024) ? W1[(size_t)(1023 - t) * COMB] : W1[t - 1023];
        g_W1frag[f] = __uint_as_float(f2tf32(v));
    } else {
        const int f2 = f - T1;
        if (f2 < NN1 * NSC * 4096) {
            const int blk = f2 >> 12, r = f2 & 4095;
            const int n1 = blk >> 2, sc = blk & 3;
            const int reg = r & 1, lane = (r >> 1) & 31, kk = (r >> 6) & 3, nt = (r >> 8) & 15;
            const int n = nt * 8 + (lane >> 2);
            const int k = n1 * 128 + sc * 32 + kk * 8 + reg * 4 + (lane & 3);
            const float v = (n < 64) ? Wsl[(size_t)n * LDIM + k] : Wint[(size_t)(n - 64) * LDIM + k];
            g_W2frag[f2] = __uint_as_float(f2tf32(v));
        }
    }
}

// ================= fused main kernel =================
__global__ void __launch_bounds__(256, 1)
fused_kernel(const float* __restrict__ xf, const float* __restrict__ he,
             const float* __restrict__ b1, const float* __restrict__ bs,
             const float* __restrict__ bi, float* __restrict__ out) {
    extern __shared__ float sm[];
    const uint32_t smb = smem_u32(sm);
    const int tid = threadIdx.x, lane = tid & 31, wid = tid >> 5;
    const int wm = wid & 3, wn = wid >> 2;
    const int m0 = blockIdx.x * TM;

    float acc1[2][8][4];
    float acc2[2][8][4];
#pragma unroll
    for (int a = 0; a < 2; ++a)
#pragma unroll
        for (int b = 0; b < 8; ++b)
#pragma unroll
            for (int c = 0; c < 4; ++c) acc2[a][b][c] = 0.f;

    // ---- staging helpers (inline) ----
    auto wsrc = [&](int s) -> const float* {
        const int n1 = s / NIT, pos = s - n1 * NIT;
        return (pos < NKC) ? g_W1frag + ((size_t)(n1 * NKC + pos) << 12)
                           : g_W2frag + ((size_t)(n1 * NSC + (pos - NKC)) << 12);
    };
    auto stage_w = [&](int s, int buf) {
        const float* src = wsrc(s) + tid * 4;
        const uint32_t dst = smb + (uint32_t)((SM_WB + buf * WBUF_F + tid * 4) << 2);
#pragma unroll
        for (int i = 0; i < 4; ++i) cp16(dst + i * 4096, src + i * 1024);
    };
    auto lda = [&](int kc, float4 (&v)[4]) {
        const float* base;
        int stride;
        if (kc < 2) { base = xf + (size_t)m0 * 64 + kc * 32; stride = 64; }
        else        { base = he + (size_t)m0 * 960 + (kc * 32 - 64); stride = 960; }
#pragma unroll
        for (int it = 0; it < 4; ++it) {
            const int idx = tid + it * 256;
            const int r = idx >> 3, c4 = idx & 7;
            v[it] = *reinterpret_cast<const float4*>(base + (size_t)r * stride + c4 * 4);
        }
    };
    auto sta = [&](const float4 (&v)[4], int buf) {
        float* ab = sm + SM_AB + buf * ABUF_F;
#pragma unroll
        for (int it = 0; it < 4; ++it) {
            const int idx = tid + it * 256;
            const int r = idx >> 3, c4 = idx & 7;
            const int kk = c4 >> 1, reghalf = (c4 & 1) * 2, rowhi = (r >> 3) & 1, mt8 = r >> 4;
            const int slotbase = (r & 7) * 4;
            const float vv[4] = {v[it].x, v[it].y, v[it].z, v[it].w};
#pragma unroll
            for (int u = 0; u < 4; ++u) {
                const int slot = (slotbase + u) ^ kk;
                ab[((kk * 8 + mt8) * 32 + slot) * 4 + reghalf + rowhi] =
                    __uint_as_float(f2tf32(vv[u]));
            }
        }
    };

    // ---- prologue: stage iteration 0 ----
    float4 av[4];
    stage_w(0, 0);
    lda(0, av);
    sta(av, 0);
    cp_commit();
    cp_wait0();
    __syncthreads();

    // ---- main pipelined loop ----
    for (int s = 0; s < S_TOT; ++s) {
        const int buf = s & 1;
        const int n1 = s / NIT;
        const int pos = s - n1 * NIT;
        const bool hn = (s + 1 < S_TOT);
        const int npos = (pos + 1 == NIT) ? 0 : pos + 1;
        const bool nextA = hn && (npos < NKC);

        if (hn) {
            stage_w(s + 1, buf ^ 1);
            if (nextA) lda(npos, av);
            cp_commit();
        }

        if (pos < NKC) {
            if (pos == 0) {
#pragma unroll
                for (int a = 0; a < 2; ++a)
#pragma unroll
                    for (int b = 0; b < 8; ++b)
#pragma unroll
                        for (int c = 0; c < 4; ++c) acc1[a][b][c] = 0.f;
            }
            mma_chunk(sm + SM_AB + buf * ABUF_F, 0, true,
                      sm + SM_WB + buf * WBUF_F, wm, wn, lane, acc1);
            if (pos == NKC - 1) {
                // epilogue1: q = tf32(relu(acc1 + b1)) -> SMEM in A-fragment layout
                const float* b1p = b1 + n1 * 128 + wn * 64;
                const int g = lane >> 2, t = lane & 3;
#pragma unroll
                for (int nt = 0; nt < 8; ++nt) {
                    const float2 bv = *reinterpret_cast<const float2*>(b1p + nt * 8 + t * 2);
                    const int kk2 = wn * 8 + nt;
#pragma unroll
                    for (int mt = 0; mt < 2; ++mt) {
                        const int mt8 = wm * 2 + mt;
#pragma unroll
                        for (int cr = 0; cr < 4; ++cr) {
                            const int e = cr & 1, r0 = cr >> 1;
                            float x = acc1[mt][nt][cr] + (e ? bv.y : bv.x);
                            x = fmaxf(x, 0.f);
                            const int c8 = 2 * t + e;
                            const int slot = g * 4 + (c8 & 3);
                            const int regp = r0 + 2 * (c8 >> 2);
                            sm[SM_Q + ((kk2 * 8 + mt8) * 32 + slot) * 4 + regp] =
                                __uint_as_float(f2tf32(x));
                        }
                    }
                }
            }
        } else {
            mma_chunk(sm + SM_Q, (pos - NKC) * 4, false,
                      sm + SM_WB + buf * WBUF_F, wm, wn, lane, acc2);
        }

        if (hn) {
            if (nextA) sta(av, buf ^ 1);
            cp_wait0();
            __syncthreads();
        }
    }

    // ---- final epilogue: acc2 -> (tanh(x+bs) | x+bi) ----
    {
        const int g = lane >> 2, t = lane & 3;
        const float* bvecs = (wn == 0) ? bs : bi;
        float* obase = out + ((wn == 1) ? (size_t)B_ROWS * 64 : 0);
#pragma unroll
        for (int nt = 0; nt < 8; ++nt) {
            const int Cl = nt * 8 + t * 2;  // 0..63 within segment
            const float2 bv = *reinterpret_cast<const float2*>(bvecs + Cl);
#pragma unroll
            for (int mt = 0; mt < 2; ++mt) {
#pragma unroll
                for (int rp = 0; rp < 2; ++rp) {
                    const int R = wm * 32 + mt * 16 + g + rp * 8;
                    float x0 = acc2[mt][nt][rp * 2 + 0] + bv.x;
                    float x1 = acc2[mt][nt][rp * 2 + 1] + bv.y;
                    if (wn == 0) { x0 = fast_tanh(x0); x1 = fast_tanh(x1); }
                    float2 o; o.x = x0; o.y = x1;
                    *reinterpret_cast<float2*>(obase + (size_t)(m0 + R) * 64 + Cl) = o;
                }
            }
        }
    }
}

// ================= launch =================
extern "C" void kernel_launch(void* const* d_in, const int* in_sizes, int n_in,
                              void* d_out, int out_size) {
    const float* xf = (const float*)d_in[0];  // x_frame [B,64]
    const float* he = (const float*)d_in[1];  // h_esn   [B,960]
    const float* W1 = (const float*)d_in[2];  // [1024,1024]
    const float* b1 = (const float*)d_in[3];  // [1024]
    const float* Ws = (const float*)d_in[4];  // [64,1024]
    const float* bs = (const float*)d_in[5];  // [64]
    const float* Wi = (const float*)d_in[6];  // [64,1024]
    const float* bi = (const float*)d_in[7];  // [64]
    float* out = (float*)d_out;               // [slope(B*64) | intercept(B*64)]

    static bool attr_set = false;
    if (!attr_set) {
        cudaFuncSetAttribute(fused_kernel, cudaFuncAttributeMaxDynamicSharedMemorySize, SMEM_BYTES);
        attr_set = true;
    }

    const int prep_total = NN1 * NKC * 4096 + NN1 * NSC * 4096;
    prep_kernel<<<(prep_total + 255) / 256, 256>>>(W1, Ws, Wi);
    fused_kernel<<<B_ROWS / TM, 256, SMEM_BYTES>>>(xf, he, b1, bs, bi, out);
}

// round 4
// speedup vs baseline: 1.0726x; 1.0726x over previous
#include <cuda_runtime.h>
#include <cstdint>

// ================= problem constants =================
constexpr int B_ROWS = 65536;
constexpr int LDIM   = 1024;   // last_dim (GEMM1 N, GEMM2 K)
constexpr int COMB   = 1024;   // frame+esn (GEMM1 K)

// ================= tiling =================
constexpr int TM   = 128;            // batch rows per CTA
constexpr int N1C  = 128;            // GEMM1 N-chunk
constexpr int KB   = 32;             // K-chunk
constexpr int NN1  = LDIM / N1C;     // 8
constexpr int NKC  = COMB / KB;      // 32 GEMM1 k-chunks per n1
constexpr int NSC  = N1C / KB;       // 4  GEMM2 k-chunks per n1
constexpr int NIT  = NKC + NSC;      // 36 iterations per n1
constexpr int S_TOT = NN1 * NIT;     // 288
constexpr int MBLKS = B_ROWS / TM;   // 512

// ================= SMEM (floats) =================
// 4-stage rings for A and W + Q staging
constexpr int SM_AB = 0;                       // 4 x 4096
constexpr int SM_WB = 4 * 4096;                // 16384
constexpr int SM_Q  = SM_WB + 4 * 4096;        // 32768
constexpr int SMEM_BYTES = (SM_Q + TM * N1C) * 4;  // 196608
static_assert(SMEM_BYTES <= 232448, "smem");

// fragment-ordered tf32 weights + activations (built by prep kernels)
__device__ __align__(16) float g_W1frag[NN1 * NKC * 4096];   // 4 MB
__device__ __align__(16) float g_W2frag[NN1 * NSC * 4096];   // 512 KB
__device__ __align__(16) float g_Afrag[(size_t)MBLKS * NKC * 4096];  // 268 MB

// ================= helpers =================
__device__ __forceinline__ uint32_t smem_u32(const void* p) {
    uint32_t a;
    asm("{ .reg .u64 t; cvta.to.shared.u64 t, %1; cvt.u32.u64 %0, t; }" : "=r"(a) : "l"(p));
    return a;
}
__device__ __forceinline__ uint32_t f2tf32(float x) {  // round-to-nearest tf32
    uint32_t r;
    asm("cvt.rna.tf32.f32 %0, %1;" : "=r"(r) : "f"(x));
    return r;
}
__device__ __forceinline__ float fast_tanh(float x) {
    float r;
    asm("tanh.approx.f32 %0, %1;" : "=f"(r) : "f"(x));
    return r;
}
__device__ __forceinline__ void cp16(uint32_t saddr, const float* gptr) {
    asm volatile("cp.async.cg.shared.global [%0], [%1], 16;"
                 :: "r"(saddr), "l"((unsigned long long)__cvta_generic_to_global(gptr)) : "memory");
}
__device__ __forceinline__ void cp_commit() { asm volatile("cp.async.commit_group;" ::: "memory"); }
__device__ __forceinline__ void cp_wait2()  { asm volatile("cp.async.wait_group 2;"  ::: "memory"); }

__device__ __forceinline__ void mma8(float (&d)[4], const uint32_t (&a)[4], const uint32_t (&b)[2]) {
    asm volatile(
        "mma.sync.aligned.m16n8k8.row.col.f32.tf32.tf32.f32 "
        "{%0,%1,%2,%3},{%4,%5,%6,%7},{%8,%9},{%0,%1,%2,%3};"
        : "+f"(d[0]), "+f"(d[1]), "+f"(d[2]), "+f"(d[3])
        : "r"(a[0]), "r"(a[1]), "r"(a[2]), "r"(a[3]), "r"(b[0]), "r"(b[1]));
}

// one K=32 chunk of mma for this warp. abase: A-fragment layout
// [kk4][mt8(8)][slot(32)][reg(4)]; wb: B-fragment layout [nt16][kk4][lane][reg2]
__device__ __forceinline__ void mma_chunk(const float* __restrict__ abase, int kkoff, bool axor,
                                          const float* __restrict__ wb,
                                          int wm, int wn, int lane, float (&acc)[2][8][4]) {
#pragma unroll
    for (int kk = 0; kk < 4; ++kk) {
        const int asl = axor ? (lane ^ kk) : lane;
        uint32_t af[2][4];
#pragma unroll
        for (int mt = 0; mt < 2; ++mt) {
            const float4 v = *reinterpret_cast<const float4*>(
                abase + ((((kkoff + kk) * 8 + wm * 2 + mt) * 32 + asl) << 2));
            af[mt][0] = __float_as_uint(v.x); af[mt][1] = __float_as_uint(v.y);
            af[mt][2] = __float_as_uint(v.z); af[mt][3] = __float_as_uint(v.w);
        }
        uint32_t bf[8][2];
#pragma unroll
        for (int nt = 0; nt < 8; ++nt) {
            const float2 v = *reinterpret_cast<const float2*>(
                wb + ((((wn * 8 + nt) * 4 + kk) * 32 + lane) << 1));
            bf[nt][0] = __float_as_uint(v.x); bf[nt][1] = __float_as_uint(v.y);
        }
#pragma unroll
        for (int mt = 0; mt < 2; ++mt)
#pragma unroll
            for (int nt = 0; nt < 8; ++nt) mma8(acc[mt][nt], af[mt], bf[nt]);
    }
}

// ================= prep: Toeplitz expand + frag shuffle + tf32 round =================
__global__ void prep_w_kernel(const float* __restrict__ W1,
                              const float* __restrict__ Wsl,
                              const float* __restrict__ Wint) {
    const int f = blockIdx.x * 256 + threadIdx.x;
    const int T1 = NN1 * NKC * 4096;
    if (f < T1) {
        const int blk = f >> 12, r = f & 4095;
        const int n1 = blk >> 5, kc = blk & 31;
        const int reg = r & 1, lane = (r >> 1) & 31, kk = (r >> 6) & 3, nt = (r >> 8) & 15;
        const int n = n1 * 128 + nt * 8 + (lane >> 2);
        const int k = kc * 32 + kk * 8 + reg * 4 + (lane & 3);
        const int t = 1023 - n + k;  // toeplitz param index
        const float v = (t < 1024) ? W1[(size_t)(1023 - t) * COMB] : W1[t - 1023];
        g_W1frag[f] = __uint_as_float(f2tf32(v));
    } else {
        const int f2 = f - T1;
        if (f2 < NN1 * NSC * 4096) {
            const int blk = f2 >> 12, r = f2 & 4095;
            const int n1 = blk >> 2, sc = blk & 3;
            const int reg = r & 1, lane = (r >> 1) & 31, kk = (r >> 6) & 3, nt = (r >> 8) & 15;
            const int n = nt * 8 + (lane >> 2);
            const int k = n1 * 128 + sc * 32 + kk * 8 + reg * 4 + (lane & 3);
            const float v = (n < 64) ? Wsl[(size_t)n * LDIM + k] : Wint[(size_t)(n - 64) * LDIM + k];
            g_W2frag[f2] = __uint_as_float(f2tf32(v));
        }
    }
}

// A fragments: per (mblk, kc) 4096-float block laid out [kk4][mt8(8)][slot32][reg4]
// reg0:(r,clo) reg1:(r+8,clo) reg2:(r,clo+4) reg3:(r+8,clo+4),
// slot = (rlow*4 + u) ^ kk  =>  rlow = (slot^kk)>>2, u = (slot^kk)&3
__global__ void prep_a_kernel(const float* __restrict__ xf, const float* __restrict__ he) {
    const size_t g = (size_t)blockIdx.x * 256 + threadIdx.x;  // one float4 per thread
    uint32_t q = (uint32_t)g;
    const int slot = q & 31;  q >>= 5;
    const int mt8  = q & 7;   q >>= 3;
    const int kk   = q & 3;   q >>= 2;
    const int kc   = q & 31;  q >>= 5;
    const int mblk = q;       // 0..511
    const int s0 = slot ^ kk;
    const int rlow = s0 >> 2, u = s0 & 3;
    const int r0 = mt8 * 16 + rlow;
    const int row0 = mblk * 128 + r0;
    const int clo = kc * 32 + kk * 8 + u;   // global k column
    auto rd = [&](int row, int col) -> float {
        return (col < 64) ? xf[(size_t)row * 64 + col] : he[(size_t)row * 960 + (col - 64)];
    };
    uint4 o;
    o.x = f2tf32(rd(row0,     clo));
    o.y = f2tf32(rd(row0 + 8, clo));
    o.z = f2tf32(rd(row0,     clo + 4));
    o.w = f2tf32(rd(row0 + 8, clo + 4));
    *reinterpret_cast<uint4*>(g_Afrag + 4 * g) = o;
}

// ================= fused main kernel =================
__global__ void __launch_bounds__(256, 1)
fused_kernel(const float* __restrict__ b1, const float* __restrict__ bs,
             const float* __restrict__ bi, float* __restrict__ out) {
    extern __shared__ float sm[];
    const uint32_t smb = smem_u32(sm);
    const int tid = threadIdx.x, lane = tid & 31, wid = tid >> 5;
    const int wm = wid & 3, wn = wid >> 2;
    const int mblk = blockIdx.x;
    const int m0 = mblk * TM;

    float acc1[2][8][4];
    float acc2[2][8][4];
#pragma unroll
    for (int a = 0; a < 2; ++a)
#pragma unroll
        for (int b = 0; b < 8; ++b)
#pragma unroll
            for (int c = 0; c < 4; ++c) acc2[a][b][c] = 0.f;

    // ---- prefetch helper: stage iteration sp into ring slot sp&3 ----
    // NOTE: dst strides are BYTES: 1024 floats = 4096 bytes per cp16 step.
    auto fetch = [&](int sp) {
        const int n1p = sp / NIT, posp = sp % NIT;
        const int slot = sp & 3;
        const float* wsrc = (posp < NKC)
            ? g_W1frag + ((size_t)(n1p * NKC + posp) << 12)
            : g_W2frag + ((size_t)(n1p * NSC + (posp - NKC)) << 12);
        const uint32_t wdst = smb + (uint32_t)((SM_WB + slot * 4096 + tid * 4) << 2);
#pragma unroll
        for (int i = 0; i < 4; ++i) cp16(wdst + i * 4096, wsrc + tid * 4 + i * 1024);
        if (posp < NKC) {
            const float* asrc = g_Afrag + (((size_t)mblk * NKC + posp) << 12);
            const uint32_t adst = smb + (uint32_t)((SM_AB + slot * 4096 + tid * 4) << 2);
#pragma unroll
            for (int i = 0; i < 4; ++i) cp16(adst + i * 4096, asrc + tid * 4 + i * 1024);
        }
    };

    // ---- prologue: 3 stages in flight ----
    fetch(0); cp_commit();
    fetch(1); cp_commit();
    fetch(2); cp_commit();

    // ---- main pipelined loop ----
    for (int s = 0; s < S_TOT; ++s) {
        cp_wait2();          // group s complete (s+1, s+2 still in flight)
        __syncthreads();     // buffers visible; ring slot (s+3)&3 free

        const int sp = s + 3;
        if (sp < S_TOT) fetch(sp);
        cp_commit();         // always commit to keep group accounting aligned

        const int n1 = s / NIT, pos = s % NIT;
        const int slot = s & 3;
        if (pos < NKC) {
            if (pos == 0) {
#pragma unroll
                for (int a = 0; a < 2; ++a)
#pragma unroll
                    for (int b = 0; b < 8; ++b)
#pragma unroll
                        for (int c = 0; c < 4; ++c) acc1[a][b][c] = 0.f;
            }
            mma_chunk(sm + SM_AB + slot * 4096, 0, true,
                      sm + SM_WB + slot * 4096, wm, wn, lane, acc1);
            if (pos == NKC - 1) {
                // epilogue1: q = tf32(relu(acc1 + b1)) -> SMEM in A-fragment layout
                const float* b1p = b1 + n1 * 128 + wn * 64;
                const int g = lane >> 2, t = lane & 3;
#pragma unroll
                for (int nt = 0; nt < 8; ++nt) {
                    const float2 bv = *reinterpret_cast<const float2*>(b1p + nt * 8 + t * 2);
                    const int kk2 = wn * 8 + nt;
#pragma unroll
                    for (int mt = 0; mt < 2; ++mt) {
                        const int mt8 = wm * 2 + mt;
#pragma unroll
                        for (int cr = 0; cr < 4; ++cr) {
                            const int e = cr & 1, r0 = cr >> 1;
                            float x = acc1[mt][nt][cr] + (e ? bv.y : bv.x);
                            x = fmaxf(x, 0.f);
                            const int c8 = 2 * t + e;
                            const int qslot = g * 4 + (c8 & 3);
                            const int regp = r0 + 2 * (c8 >> 2);
                            sm[SM_Q + ((kk2 * 8 + mt8) * 32 + qslot) * 4 + regp] =
                                __uint_as_float(f2tf32(x));
                        }
                    }
                }
            }
        } else {
            mma_chunk(sm + SM_Q, (pos - NKC) * 4, false,
                      sm + SM_WB + slot * 4096, wm, wn, lane, acc2);
        }
    }

    // ---- final epilogue: acc2 -> (tanh(x+bs) | x+bi) ----
    {
        const int g = lane >> 2, t = lane & 3;
        const float* bvecs = (wn == 0) ? bs : bi;
        float* obase = out + ((wn == 1) ? (size_t)B_ROWS * 64 : 0);
#pragma unroll
        for (int nt = 0; nt < 8; ++nt) {
            const int Cl = nt * 8 + t * 2;  // 0..63 within segment
            const float2 bv = *reinterpret_cast<const float2*>(bvecs + Cl);
#pragma unroll
            for (int mt = 0; mt < 2; ++mt) {
#pragma unroll
                for (int rp = 0; rp < 2; ++rp) {
                    const int R = wm * 32 + mt * 16 + g + rp * 8;
                    float x0 = acc2[mt][nt][rp * 2 + 0] + bv.x;
                    float x1 = acc2[mt][nt][rp * 2 + 1] + bv.y;
                    if (wn == 0) { x0 = fast_tanh(x0); x1 = fast_tanh(x1); }
                    float2 o; o.x = x0; o.y = x1;
                    *reinterpret_cast<float2*>(obase + (size_t)(m0 + R) * 64 + Cl) = o;
                }
            }
        }
    }
}

// ================= launch =================
extern "C" void kernel_launch(void* const* d_in, const int* in_sizes, int n_in,
                              void* d_out, int out_size) {
    const float* xf = (const float*)d_in[0];  // x_frame [B,64]
    const float* he = (const float*)d_in[1];  // h_esn   [B,960]
    const float* W1 = (const float*)d_in[2];  // [1024,1024]
    const float* b1 = (const float*)d_in[3];  // [1024]
    const float* Ws = (const float*)d_in[4];  // [64,1024]
    const float* bs = (const float*)d_in[5];  // [64]
    const float* Wi = (const float*)d_in[6];  // [64,1024]
    const float* bi = (const float*)d_in[7];  // [64]
    float* out = (float*)d_out;               // [slope(B*64) | intercept(B*64)]

    static bool attr_set = false;
    if (!attr_set) {
        cudaFuncSetAttribute(fused_kernel, cudaFuncAttributeMaxDynamicSharedMemorySize, SMEM_BYTES);
        attr_set = true;
    }

    const int prep_w_total = NN1 * NKC * 4096 + NN1 * NSC * 4096;
    prep_w_kernel<<<(prep_w_total + 255) / 256, 256>>>(W1, Ws, Wi);
    const size_t prep_a_blocks = ((size_t)MBLKS * NKC * 4096 / 4) / 256;  // 65536
    prep_a_kernel<<<(unsigned)prep_a_blocks, 256>>>(xf, he);
    fused_kernel<<<MBLKS, 256, SMEM_BYTES>>>(b1, bs, bi, out);
}

// round 5
// speedup vs baseline: 1.1672x; 1.0882x over previous
#include <cuda_runtime.h>
#include <cstdint>

// ================= problem constants =================
constexpr int B_ROWS = 65536;
constexpr int LDIM   = 1024;
constexpr int COMB   = 1024;

// ================= tiling =================
constexpr int TM   = 128;
constexpr int N1C  = 128;
constexpr int KB   = 32;
constexpr int NN1  = LDIM / N1C;     // 8 total n1 passes
constexpr int NN1H = NN1 / 2;        // 4 per CTA (half)
constexpr int NKC  = COMB / KB;      // 32
constexpr int NSC  = N1C / KB;       // 4
constexpr int NIT  = NKC + NSC;      // 36
constexpr int S_H  = NN1H * NIT;     // 144 iters per CTA
constexpr int MBLKS = B_ROWS / TM;   // 512
constexpr int GRID  = MBLKS * 2;     // 1024 CTAs (pairs)

// ================= SMEM (floats) =================
constexpr int SM_AB = 0;                       // 4 x 4096
constexpr int SM_WB = 4 * 4096;                // 16384
constexpr int SM_Q  = SM_WB + 4 * 4096;        // 32768
constexpr int SMEM_BYTES = (SM_Q + TM * N1C) * 4;  // 196608
static_assert(SMEM_BYTES <= 232448, "smem");

// fragment-ordered tf32 weights + activations (built by prep kernels)
__device__ __align__(16) float g_W1frag[NN1 * NKC * 4096];   // 4 MB
__device__ __align__(16) float g_W2frag[NN1 * NSC * 4096];   // 512 KB
__device__ __align__(16) float g_Afrag[(size_t)MBLKS * NKC * 4096];  // 268 MB
// pair-reduction workspace: per CTA 256 threads x 64 floats
__device__ __align__(16) float g_part[(size_t)GRID * 256 * 64];      // 64 MB
__device__ unsigned g_cnt[MBLKS];   // zero-init; reset by finisher each run

// ================= helpers =================
__device__ __forceinline__ uint32_t smem_u32(const void* p) {
    uint32_t a;
    asm("{ .reg .u64 t; cvta.to.shared.u64 t, %1; cvt.u32.u64 %0, t; }" : "=r"(a) : "l"(p));
    return a;
}
__device__ __forceinline__ uint32_t f2tf32(float x) {
    uint32_t r;
    asm("cvt.rna.tf32.f32 %0, %1;" : "=r"(r) : "f"(x));
    return r;
}
__device__ __forceinline__ float fast_tanh(float x) {
    float r;
    asm("tanh.approx.f32 %0, %1;" : "=f"(r) : "f"(x));
    return r;
}
__device__ __forceinline__ void cp16(uint32_t saddr, const float* gptr) {
    asm volatile("cp.async.cg.shared.global [%0], [%1], 16;"
                 :: "r"(saddr), "l"((unsigned long long)__cvta_generic_to_global(gptr)) : "memory");
}
__device__ __forceinline__ void cp_commit() { asm volatile("cp.async.commit_group;" ::: "memory"); }
__device__ __forceinline__ void cp_wait2()  { asm volatile("cp.async.wait_group 2;"  ::: "memory"); }
__device__ __forceinline__ void cp_wait0()  { asm volatile("cp.async.wait_group 0;"  ::: "memory"); }

__device__ __forceinline__ void mma8(float (&d)[4], const uint32_t (&a)[4], const uint32_t (&b)[2]) {
    asm volatile(
        "mma.sync.aligned.m16n8k8.row.col.f32.tf32.tf32.f32 "
        "{%0,%1,%2,%3},{%4,%5,%6,%7},{%8,%9},{%0,%1,%2,%3};"
        : "+f"(d[0]), "+f"(d[1]), "+f"(d[2]), "+f"(d[3])
        : "r"(a[0]), "r"(a[1]), "r"(a[2]), "r"(a[3]), "r"(b[0]), "r"(b[1]));
}

// one K=32 chunk. abase: [kk4][mt8(8)][slot32][reg4]; wb: [nt16][kk4][lane][reg2]
__device__ __forceinline__ void mma_chunk(const float* __restrict__ abase, int kkoff, bool axor,
                                          const float* __restrict__ wb,
                                          int wm, int wn, int lane, float (&acc)[2][8][4]) {
#pragma unroll
    for (int kk = 0; kk < 4; ++kk) {
        const int asl = axor ? (lane ^ kk) : lane;
        uint32_t af[2][4];
#pragma unroll
        for (int mt = 0; mt < 2; ++mt) {
            const float4 v = *reinterpret_cast<const float4*>(
                abase + ((((kkoff + kk) * 8 + wm * 2 + mt) * 32 + asl) << 2));
            af[mt][0] = __float_as_uint(v.x); af[mt][1] = __float_as_uint(v.y);
            af[mt][2] = __float_as_uint(v.z); af[mt][3] = __float_as_uint(v.w);
        }
        uint32_t bf[8][2];
#pragma unroll
        for (int nt = 0; nt < 8; ++nt) {
            const float2 v = *reinterpret_cast<const float2*>(
                wb + ((((wn * 8 + nt) * 4 + kk) * 32 + lane) << 1));
            bf[nt][0] = __float_as_uint(v.x); bf[nt][1] = __float_as_uint(v.y);
        }
#pragma unroll
        for (int mt = 0; mt < 2; ++mt)
#pragma unroll
            for (int nt = 0; nt < 8; ++nt) mma8(acc[mt][nt], af[mt], bf[nt]);
    }
}

// ================= prep: Toeplitz expand + frag shuffle + tf32 round =================
__global__ void prep_w_kernel(const float* __restrict__ W1,
                              const float* __restrict__ Wsl,
                              const float* __restrict__ Wint) {
    const int f = blockIdx.x * 256 + threadIdx.x;
    const int T1 = NN1 * NKC * 4096;
    if (f < T1) {
        const int blk = f >> 12, r = f & 4095;
        const int n1 = blk >> 5, kc = blk & 31;
        const int reg = r & 1, lane = (r >> 1) & 31, kk = (r >> 6) & 3, nt = (r >> 8) & 15;
        const int n = n1 * 128 + nt * 8 + (lane >> 2);
        const int k = kc * 32 + kk * 8 + reg * 4 + (lane & 3);
        const int t = 1023 - n + k;
        const float v = (t < 1024) ? W1[(size_t)(1023 - t) * COMB] : W1[t - 1023];
        g_W1frag[f] = __uint_as_float(f2tf32(v));
    } else {
        const int f2 = f - T1;
        if (f2 < NN1 * NSC * 4096) {
            const int blk = f2 >> 12, r = f2 & 4095;
            const int n1 = blk >> 2, sc = blk & 3;
            const int reg = r & 1, lane = (r >> 1) & 31, kk = (r >> 6) & 3, nt = (r >> 8) & 15;
            const int n = nt * 8 + (lane >> 2);
            const int k = n1 * 128 + sc * 32 + kk * 8 + reg * 4 + (lane & 3);
            const float v = (n < 64) ? Wsl[(size_t)n * LDIM + k] : Wint[(size_t)(n - 64) * LDIM + k];
            g_W2frag[f2] = __uint_as_float(f2tf32(v));
        }
    }
}

__global__ void prep_a_kernel(const float* __restrict__ xf, const float* __restrict__ he) {
    const size_t g = (size_t)blockIdx.x * 256 + threadIdx.x;
    uint32_t q = (uint32_t)g;
    const int slot = q & 31;  q >>= 5;
    const int mt8  = q & 7;   q >>= 3;
    const int kk   = q & 3;   q >>= 2;
    const int kc   = q & 31;  q >>= 5;
    const int mblk = q;
    const int s0 = slot ^ kk;
    const int rlow = s0 >> 2, u = s0 & 3;
    const int r0 = mt8 * 16 + rlow;
    const int row0 = mblk * 128 + r0;
    const int clo = kc * 32 + kk * 8 + u;
    auto rd = [&](int row, int col) -> float {
        return (col < 64) ? xf[(size_t)row * 64 + col] : he[(size_t)row * 960 + (col - 64)];
    };
    uint4 o;
    o.x = f2tf32(rd(row0,     clo));
    o.y = f2tf32(rd(row0 + 8, clo));
    o.z = f2tf32(rd(row0,     clo + 4));
    o.w = f2tf32(rd(row0 + 8, clo + 4));
    *reinterpret_cast<uint4*>(g_Afrag + 4 * g) = o;
}

// ================= fused main kernel (pair-split over n1) =================
__global__ void __launch_bounds__(256, 1)
fused_kernel(const float* __restrict__ b1, const float* __restrict__ bs,
             const float* __restrict__ bi, float* __restrict__ out) {
    extern __shared__ float sm[];
    const uint32_t smb = smem_u32(sm);
    const int tid = threadIdx.x, lane = tid & 31, wid = tid >> 5;
    const int wm = wid & 3, wn = wid >> 2;
    const int bid  = blockIdx.x;
    const int mblk = bid >> 1;        // pair id
    const int half = bid & 1;         // n1 half: [half*4, half*4+4)
    const int m0 = mblk * TM;

    float acc1[2][8][4];
    float acc2[2][8][4];
#pragma unroll
    for (int a = 0; a < 2; ++a)
#pragma unroll
        for (int b = 0; b < 8; ++b)
#pragma unroll
            for (int c = 0; c < 4; ++c) acc2[a][b][c] = 0.f;

    auto fetch = [&](int sp) {
        const int n1p = half * NN1H + sp / NIT, posp = sp % NIT;
        const int slot = sp & 3;
        const float* wsrc = (posp < NKC)
            ? g_W1frag + ((size_t)(n1p * NKC + posp) << 12)
            : g_W2frag + ((size_t)(n1p * NSC + (posp - NKC)) << 12);
        const uint32_t wdst = smb + (uint32_t)((SM_WB + slot * 4096 + tid * 4) << 2);
#pragma unroll
        for (int i = 0; i < 4; ++i) cp16(wdst + i * 4096, wsrc + tid * 4 + i * 1024);
        if (posp < NKC) {
            const float* asrc = g_Afrag + (((size_t)mblk * NKC + posp) << 12);
            const uint32_t adst = smb + (uint32_t)((SM_AB + slot * 4096 + tid * 4) << 2);
#pragma unroll
            for (int i = 0; i < 4; ++i) cp16(adst + i * 4096, asrc + tid * 4 + i * 1024);
        }
    };

    fetch(0); cp_commit();
    fetch(1); cp_commit();
    fetch(2); cp_commit();

    for (int s = 0; s < S_H; ++s) {
        cp_wait2();
        __syncthreads();

        const int sp = s + 3;
        if (sp < S_H) fetch(sp);
        cp_commit();

        const int n1l = s / NIT, pos = s % NIT;
        const int n1g = half * NN1H + n1l;
        const int slot = s & 3;
        if (pos < NKC) {
            if (pos == 0) {
#pragma unroll
                for (int a = 0; a < 2; ++a)
#pragma unroll
                    for (int b = 0; b < 8; ++b)
#pragma unroll
                        for (int c = 0; c < 4; ++c) acc1[a][b][c] = 0.f;
            }
            mma_chunk(sm + SM_AB + slot * 4096, 0, true,
                      sm + SM_WB + slot * 4096, wm, wn, lane, acc1);
            if (pos == NKC - 1) {
                // epilogue1: q = tf32(relu(acc1 + b1)) -> SMEM in A-fragment layout
                const float* b1p = b1 + n1g * 128 + wn * 64;
                const int g = lane >> 2, t = lane & 3;
#pragma unroll
                for (int nt = 0; nt < 8; ++nt) {
                    const float2 bv = *reinterpret_cast<const float2*>(b1p + nt * 8 + t * 2);
                    const int kk2 = wn * 8 + nt;
#pragma unroll
                    for (int mt = 0; mt < 2; ++mt) {
                        const int mt8 = wm * 2 + mt;
#pragma unroll
                        for (int cr = 0; cr < 4; ++cr) {
                            const int e = cr & 1, r0 = cr >> 1;
                            float x = acc1[mt][nt][cr] + (e ? bv.y : bv.x);
                            x = fmaxf(x, 0.f);
                            const int c8 = 2 * t + e;
                            const int qslot = g * 4 + (c8 & 3);
                            const int regp = r0 + 2 * (c8 >> 2);
                            sm[SM_Q + ((kk2 * 8 + mt8) * 32 + qslot) * 4 + regp] =
                                __uint_as_float(f2tf32(x));
                        }
                    }
                }
            }
        } else {
            mma_chunk(sm + SM_Q, (pos - NKC) * 4, false,
                      sm + SM_WB + slot * 4096, wm, wn, lane, acc2);
        }
    }
    cp_wait0();   // retire any tail groups before we may exit early

    // ---- pair reduction: store partial acc2, second arriver finishes ----
    {
        float* wp = g_part + ((size_t)bid * 256 + tid) * 64;
#pragma unroll
        for (int mt = 0; mt < 2; ++mt)
#pragma unroll
            for (int nt = 0; nt < 8; ++nt) {
                float4 v;
                v.x = acc2[mt][nt][0]; v.y = acc2[mt][nt][1];
                v.z = acc2[mt][nt][2]; v.w = acc2[mt][nt][3];
                *reinterpret_cast<float4*>(wp + (mt * 8 + nt) * 4) = v;
            }
        __threadfence();   // release: my stores visible before my arrival
        __syncthreads();
        if (tid == 0) {
            unsigned old = atomicAdd(&g_cnt[mblk], 1u);
            *reinterpret_cast<unsigned*>(&sm[SM_Q]) = old;
        }
        __syncthreads();
        const unsigned old = *reinterpret_cast<const unsigned*>(&sm[SM_Q]);
        if (old == 0u) return;   // first arriver: partner will finish
        __threadfence();         // acquire: partner's partial now visible
        const float* pp = g_part + ((size_t)(bid ^ 1) * 256 + tid) * 64;
#pragma unroll
        for (int mt = 0; mt < 2; ++mt)
#pragma unroll
            for (int nt = 0; nt < 8; ++nt) {
                const float4 v = *reinterpret_cast<const float4*>(pp + (mt * 8 + nt) * 4);
                acc2[mt][nt][0] += v.x; acc2[mt][nt][1] += v.y;
                acc2[mt][nt][2] += v.z; acc2[mt][nt][3] += v.w;
            }
    }

    // ---- final epilogue (finisher only): acc2 -> (tanh(x+bs) | x+bi) ----
    {
        const int g = lane >> 2, t = lane & 3;
        const float* bvecs = (wn == 0) ? bs : bi;
        float* obase = out + ((wn == 1) ? (size_t)B_ROWS * 64 : 0);
#pragma unroll
        for (int nt = 0; nt < 8; ++nt) {
            const int Cl = nt * 8 + t * 2;
            const float2 bv = *reinterpret_cast<const float2*>(bvecs + Cl);
#pragma unroll
            for (int mt = 0; mt < 2; ++mt) {
#pragma unroll
                for (int rp = 0; rp < 2; ++rp) {
                    const int R = wm * 32 + mt * 16 + g + rp * 8;
                    float x0 = acc2[mt][nt][rp * 2 + 0] + bv.x;
                    float x1 = acc2[mt][nt][rp * 2 + 1] + bv.y;
                    if (wn == 0) { x0 = fast_tanh(x0); x1 = fast_tanh(x1); }
                    float2 o; o.x = x0; o.y = x1;
                    *reinterpret_cast<float2*>(obase + (size_t)(m0 + R) * 64 + Cl) = o;
                }
            }
        }
    }
    __syncthreads();
    if (tid == 0) g_cnt[mblk] = 0u;   // reset for the next graph replay
}

// ================= launch =================
extern "C" void kernel_launch(void* const* d_in, const int* in_sizes, int n_in,
                              void* d_out, int out_size) {
    const float* xf = (const float*)d_in[0];
    const float* he = (const float*)d_in[1];
    const float* W1 = (const float*)d_in[2];
    const float* b1 = (const float*)d_in[3];
    const float* Ws = (const float*)d_in[4];
    const float* bs = (const float*)d_in[5];
    const float* Wi = (const float*)d_in[6];
    const float* bi = (const float*)d_in[7];
    float* out = (float*)d_out;

    static bool attr_set = false;
    if (!attr_set) {
        cudaFuncSetAttribute(fused_kernel, cudaFuncAttributeMaxDynamicSharedMemorySize, SMEM_BYTES);
        attr_set = true;
    }

    const int prep_w_total = NN1 * NKC * 4096 + NN1 * NSC * 4096;
    prep_w_kernel<<<(prep_w_total + 255) / 256, 256>>>(W1, Ws, Wi);
    const size_t prep_a_blocks = ((size_t)MBLKS * NKC * 4096 / 4) / 256;
    prep_a_kernel<<<(unsigned)prep_a_blocks, 256>>>(xf, he);
    fused_kernel<<<GRID, 256, SMEM_BYTES>>>(b1, bs, bi, out);
}

// round 6
// speedup vs baseline: 1.1732x; 1.0051x over previous
#include <cuda_runtime.h>
#include <cstdint>

// ================= problem constants =================
constexpr int B_ROWS = 65536;
constexpr int LDIM   = 1024;
constexpr int COMB   = 1024;

// ================= tiling =================
constexpr int TM   = 128;
constexpr int N1C  = 128;
constexpr int KB   = 32;
constexpr int NN1  = LDIM / N1C;     // 8 total n1 passes
constexpr int NN1H = NN1 / 2;        // 4 per CTA (half)
constexpr int NKC  = COMB / KB;      // 32
constexpr int NSC  = N1C / KB;       // 4
constexpr int NIT  = NKC + NSC;      // 36
constexpr int S_H  = NN1H * NIT;     // 144 iters per CTA
constexpr int MBLKS = B_ROWS / TM;   // 512
constexpr int GRID  = MBLKS * 2;     // 1024 CTAs (pairs)
constexpr int NTHR  = 512;           // 16 warps, 4x4 warp grid, 32x32 warp tiles

// ================= SMEM (floats) =================
constexpr int SM_AB = 0;                       // 4 x 4096
constexpr int SM_WB = 4 * 4096;                // 16384
constexpr int SM_Q  = SM_WB + 4 * 4096;        // 32768
constexpr int SMEM_BYTES = (SM_Q + TM * N1C) * 4;  // 196608
static_assert(SMEM_BYTES <= 232448, "smem");

// fragment-ordered tf32 weights + activations (built by prep kernels)
__device__ __align__(16) float g_W1frag[NN1 * NKC * 4096];   // 4 MB
__device__ __align__(16) float g_W2frag[NN1 * NSC * 4096];   // 512 KB
__device__ __align__(16) float g_Afrag[(size_t)MBLKS * NKC * 4096];  // 268 MB
// pair-reduction workspace: per CTA 512 threads x 32 floats
__device__ __align__(16) float g_part[(size_t)GRID * NTHR * 32];     // 64 MB
__device__ unsigned g_cnt[MBLKS];   // zero-init; finisher resets each run

// ================= helpers =================
__device__ __forceinline__ uint32_t smem_u32(const void* p) {
    uint32_t a;
    asm("{ .reg .u64 t; cvta.to.shared.u64 t, %1; cvt.u32.u64 %0, t; }" : "=r"(a) : "l"(p));
    return a;
}
__device__ __forceinline__ uint32_t f2tf32(float x) {
    uint32_t r;
    asm("cvt.rna.tf32.f32 %0, %1;" : "=r"(r) : "f"(x));
    return r;
}
__device__ __forceinline__ float fast_tanh(float x) {
    float r;
    asm("tanh.approx.f32 %0, %1;" : "=f"(r) : "f"(x));
    return r;
}
__device__ __forceinline__ void cp16(uint32_t saddr, const float* gptr) {
    asm volatile("cp.async.cg.shared.global [%0], [%1], 16;"
                 :: "r"(saddr), "l"((unsigned long long)__cvta_generic_to_global(gptr)) : "memory");
}
__device__ __forceinline__ void cp_commit() { asm volatile("cp.async.commit_group;" ::: "memory"); }
__device__ __forceinline__ void cp_wait2()  { asm volatile("cp.async.wait_group 2;"  ::: "memory"); }
__device__ __forceinline__ void cp_wait0()  { asm volatile("cp.async.wait_group 0;"  ::: "memory"); }

__device__ __forceinline__ void mma8(float (&d)[4], const uint32_t (&a)[4], const uint32_t (&b)[2]) {
    asm volatile(
        "mma.sync.aligned.m16n8k8.row.col.f32.tf32.tf32.f32 "
        "{%0,%1,%2,%3},{%4,%5,%6,%7},{%8,%9},{%0,%1,%2,%3};"
        : "+f"(d[0]), "+f"(d[1]), "+f"(d[2]), "+f"(d[3])
        : "r"(a[0]), "r"(a[1]), "r"(a[2]), "r"(a[3]), "r"(b[0]), "r"(b[1]));
}

// one K=32 chunk, 32x32 warp tile. abase: [kk4][mt8(8)][slot32][reg4];
// wb: [nt16][kk4][lane][reg2], this warp uses nt = wn*4 .. wn*4+3
__device__ __forceinline__ void mma_chunk(const float* __restrict__ abase, int kkoff, bool axor,
                                          const float* __restrict__ wb,
                                          int wm, int wn, int lane, float (&acc)[2][4][4]) {
#pragma unroll
    for (int kk = 0; kk < 4; ++kk) {
        const int asl = axor ? (lane ^ kk) : lane;
        uint32_t af[2][4];
#pragma unroll
        for (int mt = 0; mt < 2; ++mt) {
            const float4 v = *reinterpret_cast<const float4*>(
                abase + ((((kkoff + kk) * 8 + wm * 2 + mt) * 32 + asl) << 2));
            af[mt][0] = __float_as_uint(v.x); af[mt][1] = __float_as_uint(v.y);
            af[mt][2] = __float_as_uint(v.z); af[mt][3] = __float_as_uint(v.w);
        }
        uint32_t bf[4][2];
#pragma unroll
        for (int nt = 0; nt < 4; ++nt) {
            const float2 v = *reinterpret_cast<const float2*>(
                wb + ((((wn * 4 + nt) * 4 + kk) * 32 + lane) << 1));
            bf[nt][0] = __float_as_uint(v.x); bf[nt][1] = __float_as_uint(v.y);
        }
#pragma unroll
        for (int mt = 0; mt < 2; ++mt)
#pragma unroll
            for (int nt = 0; nt < 4; ++nt) mma8(acc[mt][nt], af[mt], bf[nt]);
    }
}

// ================= prep: Toeplitz expand + frag shuffle + tf32 round =================
__global__ void prep_w_kernel(const float* __restrict__ W1,
                              const float* __restrict__ Wsl,
                              const float* __restrict__ Wint) {
    const int f = blockIdx.x * 256 + threadIdx.x;
    const int T1 = NN1 * NKC * 4096;
    if (f < T1) {
        const int blk = f >> 12, r = f & 4095;
        const int n1 = blk >> 5, kc = blk & 31;
        const int reg = r & 1, lane = (r >> 1) & 31, kk = (r >> 6) & 3, nt = (r >> 8) & 15;
        const int n = n1 * 128 + nt * 8 + (lane >> 2);
        const int k = kc * 32 + kk * 8 + reg * 4 + (lane & 3);
        const int t = 1023 - n + k;
        const float v = (t < 1024) ? W1[(size_t)(1023 - t) * COMB] : W1[t - 1023];
        g_W1frag[f] = __uint_as_float(f2tf32(v));
    } else {
        const int f2 = f - T1;
        if (f2 < NN1 * NSC * 4096) {
            const int blk = f2 >> 12, r = f2 & 4095;
            const int n1 = blk >> 2, sc = blk & 3;
            const int reg = r & 1, lane = (r >> 1) & 31, kk = (r >> 6) & 3, nt = (r >> 8) & 15;
            const int n = nt * 8 + (lane >> 2);
            const int k = n1 * 128 + sc * 32 + kk * 8 + reg * 4 + (lane & 3);
            const float v = (n < 64) ? Wsl[(size_t)n * LDIM + k] : Wint[(size_t)(n - 64) * LDIM + k];
            g_W2frag[f2] = __uint_as_float(f2tf32(v));
        }
    }
}

__global__ void prep_a_kernel(const float* __restrict__ xf, const float* __restrict__ he) {
    const size_t g = (size_t)blockIdx.x * 256 + threadIdx.x;
    uint32_t q = (uint32_t)g;
    const int slot = q & 31;  q >>= 5;
    const int mt8  = q & 7;   q >>= 3;
    const int kk   = q & 3;   q >>= 2;
    const int kc   = q & 31;  q >>= 5;
    const int mblk = q;
    const int s0 = slot ^ kk;
    const int rlow = s0 >> 2, u = s0 & 3;
    const int r0 = mt8 * 16 + rlow;
    const int row0 = mblk * 128 + r0;
    const int clo = kc * 32 + kk * 8 + u;
    auto rd = [&](int row, int col) -> float {
        return (col < 64) ? xf[(size_t)row * 64 + col] : he[(size_t)row * 960 + (col - 64)];
    };
    uint4 o;
    o.x = f2tf32(rd(row0,     clo));
    o.y = f2tf32(rd(row0 + 8, clo));
    o.z = f2tf32(rd(row0,     clo + 4));
    o.w = f2tf32(rd(row0 + 8, clo + 4));
    *reinterpret_cast<uint4*>(g_Afrag + 4 * g) = o;
}

// ================= fused main kernel (pair-split over n1, 16 warps) =================
__global__ void __launch_bounds__(NTHR, 1)
fused_kernel(const float* __restrict__ b1, const float* __restrict__ bs,
             const float* __restrict__ bi, float* __restrict__ out) {
    extern __shared__ float sm[];
    const uint32_t smb = smem_u32(sm);
    const int tid = threadIdx.x, lane = tid & 31, wid = tid >> 5;
    const int wm = wid & 3, wn = wid >> 2;   // 4x4 warp grid
    const int bid  = blockIdx.x;
    const int mblk = bid >> 1;
    const int half = bid & 1;
    const int m0 = mblk * TM;

    float acc1[2][4][4];
    float acc2[2][4][4];
#pragma unroll
    for (int a = 0; a < 2; ++a)
#pragma unroll
        for (int b = 0; b < 4; ++b)
#pragma unroll
            for (int c = 0; c < 4; ++c) acc2[a][b][c] = 0.f;

    // stage iteration sp into ring slot sp&3 (512 threads: 2 float4 each per buffer)
    auto fetch = [&](int sp) {
        const int n1p = half * NN1H + sp / NIT, posp = sp % NIT;
        const int slot = sp & 3;
        const float* wsrc = (posp < NKC)
            ? g_W1frag + ((size_t)(n1p * NKC + posp) << 12)
            : g_W2frag + ((size_t)(n1p * NSC + (posp - NKC)) << 12);
        const uint32_t wdst = smb + (uint32_t)((SM_WB + slot * 4096 + tid * 4) << 2);
#pragma unroll
        for (int i = 0; i < 2; ++i) cp16(wdst + i * 8192, wsrc + tid * 4 + i * 2048);
        if (posp < NKC) {
            const float* asrc = g_Afrag + (((size_t)mblk * NKC + posp) << 12);
            const uint32_t adst = smb + (uint32_t)((SM_AB + slot * 4096 + tid * 4) << 2);
#pragma unroll
            for (int i = 0; i < 2; ++i) cp16(adst + i * 8192, asrc + tid * 4 + i * 2048);
        }
    };

    fetch(0); cp_commit();
    fetch(1); cp_commit();
    fetch(2); cp_commit();

    for (int s = 0; s < S_H; ++s) {
        cp_wait2();
        __syncthreads();

        const int sp = s + 3;
        if (sp < S_H) fetch(sp);
        cp_commit();

        const int n1l = s / NIT, pos = s % NIT;
        const int n1g = half * NN1H + n1l;
        const int slot = s & 3;
        if (pos < NKC) {
            if (pos == 0) {
#pragma unroll
                for (int a = 0; a < 2; ++a)
#pragma unroll
                    for (int b = 0; b < 4; ++b)
#pragma unroll
                        for (int c = 0; c < 4; ++c) acc1[a][b][c] = 0.f;
            }
            mma_chunk(sm + SM_AB + slot * 4096, 0, true,
                      sm + SM_WB + slot * 4096, wm, wn, lane, acc1);
            if (pos == NKC - 1) {
                // epilogue1: q = tf32(relu(acc1 + b1)) -> SMEM in A-fragment layout
                const float* b1p = b1 + n1g * 128 + wn * 32;
                const int g = lane >> 2, t = lane & 3;
#pragma unroll
                for (int nt = 0; nt < 4; ++nt) {
                    const float2 bv = *reinterpret_cast<const float2*>(b1p + nt * 8 + t * 2);
                    const int kk2 = wn * 4 + nt;
#pragma unroll
                    for (int mt = 0; mt < 2; ++mt) {
                        const int mt8 = wm * 2 + mt;
#pragma unroll
                        for (int cr = 0; cr < 4; ++cr) {
                            const int e = cr & 1, r0 = cr >> 1;
                            float x = acc1[mt][nt][cr] + (e ? bv.y : bv.x);
                            x = fmaxf(x, 0.f);
                            const int c8 = 2 * t + e;
                            const int qslot = g * 4 + (c8 & 3);
                            const int regp = r0 + 2 * (c8 >> 2);
                            sm[SM_Q + ((kk2 * 8 + mt8) * 32 + qslot) * 4 + regp] =
                                __uint_as_float(f2tf32(x));
                        }
                    }
                }
            }
        } else {
            mma_chunk(sm + SM_Q, (pos - NKC) * 4, false,
                      sm + SM_WB + slot * 4096, wm, wn, lane, acc2);
        }
    }
    cp_wait0();

    // ---- pair reduction: store partial acc2, second arriver finishes ----
    {
        float* wp = g_part + ((size_t)bid * NTHR + tid) * 32;
#pragma unroll
        for (int mt = 0; mt < 2; ++mt)
#pragma unroll
            for (int nt = 0; nt < 4; ++nt) {
                float4 v;
                v.x = acc2[mt][nt][0]; v.y = acc2[mt][nt][1];
                v.z = acc2[mt][nt][2]; v.w = acc2[mt][nt][3];
                *reinterpret_cast<float4*>(wp + (mt * 4 + nt) * 4) = v;
            }
        __threadfence();
        __syncthreads();
        if (tid == 0) {
            unsigned old = atomicAdd(&g_cnt[mblk], 1u);
            *reinterpret_cast<unsigned*>(&sm[SM_Q]) = old;
        }
        __syncthreads();
        const unsigned old = *reinterpret_cast<const unsigned*>(&sm[SM_Q]);
        if (old == 0u) return;   // first arriver: partner finishes
        __threadfence();
        const float* pp = g_part + ((size_t)(bid ^ 1) * NTHR + tid) * 32;
#pragma unroll
        for (int mt = 0; mt < 2; ++mt)
#pragma unroll
            for (int nt = 0; nt < 4; ++nt) {
                const float4 v = *reinterpret_cast<const float4*>(pp + (mt * 4 + nt) * 4);
                acc2[mt][nt][0] += v.x; acc2[mt][nt][1] += v.y;
                acc2[mt][nt][2] += v.z; acc2[mt][nt][3] += v.w;
            }
    }

    // ---- final epilogue (finisher only): acc2 -> (tanh(x+bs) | x+bi) ----
    {
        const int g = lane >> 2, t = lane & 3;
        const int seg = wn >> 1;                 // 0: slope, 1: intercept
        const int cb  = (wn & 1) * 32;           // column base within segment
        const float* bvecs = seg ? bi : bs;
        float* obase = out + (seg ? (size_t)B_ROWS * 64 : 0);
#pragma unroll
        for (int nt = 0; nt < 4; ++nt) {
            const int Cl = cb + nt * 8 + t * 2;
            const float2 bv = *reinterpret_cast<const float2*>(bvecs + Cl);
#pragma unroll
            for (int mt = 0; mt < 2; ++mt) {
#pragma unroll
                for (int rp = 0; rp < 2; ++rp) {
                    const int R = wm * 32 + mt * 16 + g + rp * 8;
                    float x0 = acc2[mt][nt][rp * 2 + 0] + bv.x;
                    float x1 = acc2[mt][nt][rp * 2 + 1] + bv.y;
                    if (seg == 0) { x0 = fast_tanh(x0); x1 = fast_tanh(x1); }
                    float2 o; o.x = x0; o.y = x1;
                    *reinterpret_cast<float2*>(obase + (size_t)(m0 + R) * 64 + Cl) = o;
                }
            }
        }
    }
    __syncthreads();
    if (tid == 0) g_cnt[mblk] = 0u;
}

// ================= launch =================
extern "C" void kernel_launch(void* const* d_in, const int* in_sizes, int n_in,
                              void* d_out, int out_size) {
    const float* xf = (const float*)d_in[0];
    const float* he = (const float*)d_in[1];
    const float* W1 = (const float*)d_in[2];
    const float* b1 = (const float*)d_in[3];
    const float* Ws = (const float*)d_in[4];
    const float* bs = (const float*)d_in[5];
    const float* Wi = (const float*)d_in[6];
    const float* bi = (const float*)d_in[7];
    float* out = (float*)d_out;

    static bool attr_set = false;
    if (!attr_set) {
        cudaFuncSetAttribute(fused_kernel, cudaFuncAttributeMaxDynamicSharedMemorySize, SMEM_BYTES);
        attr_set = true;
    }

    const int prep_w_total = NN1 * NKC * 4096 + NN1 * NSC * 4096;
    prep_w_kernel<<<(prep_w_total + 255) / 256, 256>>>(W1, Ws, Wi);
    const size_t prep_a_blocks = ((size_t)MBLKS * NKC * 4096 / 4) / 256;
    prep_a_kernel<<<(unsigned)prep_a_blocks, 256>>>(xf, he);
    fused_kernel<<<GRID, NTHR, SMEM_BYTES>>>(b1, bs, bi, out);
}

// round 7
// speedup vs baseline: 1.3154x; 1.1212x over previous
#include <cuda_runtime.h>
#include <cstdint>

// ================= problem constants =================
constexpr int B_ROWS = 65536;
constexpr int LDIM   = 1024;
constexpr int COMB   = 1024;

// ================= tiling =================
constexpr int TM   = 64;             // batch rows per CTA (2 CTAs/SM)
constexpr int N1C  = 128;
constexpr int KB   = 32;
constexpr int NN1  = LDIM / N1C;     // 8 n1 passes total
constexpr int NN1H = NN1 / 2;        // 4 per CTA (pair half)
constexpr int NKC  = COMB / KB;      // 32
constexpr int NSC  = N1C / KB;       // 4
constexpr int NIT  = NKC + NSC;      // 36
constexpr int S_H  = NN1H * NIT;     // 144 iters per CTA
constexpr int MBLK128 = B_ROWS / 128;    // 512 (A-frag blocks)
constexpr int MBLKS   = B_ROWS / TM;     // 1024
constexpr int GRID    = MBLKS * 2;       // 2048 CTAs
constexpr int NTHR    = 256;             // 8 warps: 2 wm x 4 wn, 32x32 tiles

// ================= SMEM (floats) =================
constexpr int ASZ  = TM * KB;              // 2048
constexpr int WSZ  = N1C * KB;             // 4096
constexpr int SM_AB = 0;                   // 3 slots x 2048
constexpr int SM_WB = 3 * ASZ;             // 6144
constexpr int SM_Q  = SM_WB + 3 * WSZ;     // 18432
constexpr int Q_F   = TM * N1C / 2 * 2;    // 8192 (64x128)
constexpr int SMEM_BYTES = (SM_Q + Q_F) * 4;   // 106496
static_assert(SMEM_BYTES <= 116224, "smem per CTA (2/SM)");

// fragment-ordered tf32 weights + activations (built by prep kernels)
__device__ __align__(16) float g_W1frag[NN1 * NKC * 4096];   // 4 MB
__device__ __align__(16) float g_W2frag[NN1 * NSC * 4096];   // 512 KB
// A frags per 128-row block: [kc][kk4][mt8(8)][slot32][reg4]
__device__ __align__(16) float g_Afrag[(size_t)MBLK128 * NKC * 4096];  // 268 MB
// pair-reduction workspace
__device__ __align__(16) float g_part[(size_t)GRID * NTHR * 32];       // 64 MB
__device__ unsigned g_cnt[MBLKS];   // zero-init; finisher resets each run

// ================= helpers =================
__device__ __forceinline__ uint32_t smem_u32(const void* p) {
    uint32_t a;
    asm("{ .reg .u64 t; cvta.to.shared.u64 t, %1; cvt.u32.u64 %0, t; }" : "=r"(a) : "l"(p));
    return a;
}
__device__ __forceinline__ uint32_t f2tf32(float x) {
    uint32_t r;
    asm("cvt.rna.tf32.f32 %0, %1;" : "=r"(r) : "f"(x));
    return r;
}
__device__ __forceinline__ float fast_tanh(float x) {
    float r;
    asm("tanh.approx.f32 %0, %1;" : "=f"(r) : "f"(x));
    return r;
}
__device__ __forceinline__ void cp16(uint32_t saddr, const float* gptr) {
    asm volatile("cp.async.cg.shared.global [%0], [%1], 16;"
                 :: "r"(saddr), "l"((unsigned long long)__cvta_generic_to_global(gptr)) : "memory");
}
__device__ __forceinline__ void cp_commit() { asm volatile("cp.async.commit_group;" ::: "memory"); }
__device__ __forceinline__ void cp_wait1()  { asm volatile("cp.async.wait_group 1;"  ::: "memory"); }
__device__ __forceinline__ void cp_wait0()  { asm volatile("cp.async.wait_group 0;"  ::: "memory"); }

__device__ __forceinline__ void mma8(float (&d)[4], const uint32_t (&a)[4], const uint32_t (&b)[2]) {
    asm volatile(
        "mma.sync.aligned.m16n8k8.row.col.f32.tf32.tf32.f32 "
        "{%0,%1,%2,%3},{%4,%5,%6,%7},{%8,%9},{%0,%1,%2,%3};"
        : "+f"(d[0]), "+f"(d[1]), "+f"(d[2]), "+f"(d[3])
        : "r"(a[0]), "r"(a[1]), "r"(a[2]), "r"(a[3]), "r"(b[0]), "r"(b[1]));
}

// one K=32 chunk, 32x32 warp tile on a 64-row CTA tile.
// abase: [kk4][mt4(4)][slot32][reg4]; wb: [nt16][kk4][lane][reg2], warp uses nt=wn*4..+3
__device__ __forceinline__ void mma_chunk(const float* __restrict__ abase, int kkoff, bool axor,
                                          const float* __restrict__ wb,
                                          int wm, int wn, int lane, float (&acc)[2][4][4]) {
#pragma unroll
    for (int kk = 0; kk < 4; ++kk) {
        const int asl = axor ? (lane ^ kk) : lane;
        uint32_t af[2][4];
#pragma unroll
        for (int mt = 0; mt < 2; ++mt) {
            const float4 v = *reinterpret_cast<const float4*>(
                abase + ((((kkoff + kk) * 4 + wm * 2 + mt) * 32 + asl) << 2));
            af[mt][0] = __float_as_uint(v.x); af[mt][1] = __float_as_uint(v.y);
            af[mt][2] = __float_as_uint(v.z); af[mt][3] = __float_as_uint(v.w);
        }
        uint32_t bf[4][2];
#pragma unroll
        for (int nt = 0; nt < 4; ++nt) {
            const float2 v = *reinterpret_cast<const float2*>(
                wb + ((((wn * 4 + nt) * 4 + kk) * 32 + lane) << 1));
            bf[nt][0] = __float_as_uint(v.x); bf[nt][1] = __float_as_uint(v.y);
        }
#pragma unroll
        for (int mt = 0; mt < 2; ++mt)
#pragma unroll
            for (int nt = 0; nt < 4; ++nt) mma8(acc[mt][nt], af[mt], bf[nt]);
    }
}

// ================= prep: Toeplitz expand + frag shuffle + tf32 round =================
__global__ void prep_w_kernel(const float* __restrict__ W1,
                              const float* __restrict__ Wsl,
                              const float* __restrict__ Wint) {
    const int f = blockIdx.x * 256 + threadIdx.x;
    const int T1 = NN1 * NKC * 4096;
    if (f < T1) {
        const int blk = f >> 12, r = f & 4095;
        const int n1 = blk >> 5, kc = blk & 31;
        const int reg = r & 1, lane = (r >> 1) & 31, kk = (r >> 6) & 3, nt = (r >> 8) & 15;
        const int n = n1 * 128 + nt * 8 + (lane >> 2);
        const int k = kc * 32 + kk * 8 + reg * 4 + (lane & 3);
        const int t = 1023 - n + k;
        const float v = (t < 1024) ? W1[(size_t)(1023 - t) * COMB] : W1[t - 1023];
        g_W1frag[f] = __uint_as_float(f2tf32(v));
    } else {
        const int f2 = f - T1;
        if (f2 < NN1 * NSC * 4096) {
            const int blk = f2 >> 12, r = f2 & 4095;
            const int n1 = blk >> 2, sc = blk & 3;
            const int reg = r & 1, lane = (r >> 1) & 31, kk = (r >> 6) & 3, nt = (r >> 8) & 15;
            const int n = nt * 8 + (lane >> 2);
            const int k = n1 * 128 + sc * 32 + kk * 8 + reg * 4 + (lane & 3);
            const float v = (n < 64) ? Wsl[(size_t)n * LDIM + k] : Wint[(size_t)(n - 64) * LDIM + k];
            g_W2frag[f2] = __uint_as_float(f2tf32(v));
        }
    }
}

__global__ void prep_a_kernel(const float* __restrict__ xf, const float* __restrict__ he) {
    const size_t g = (size_t)blockIdx.x * 256 + threadIdx.x;
    uint32_t q = (uint32_t)g;
    const int slot = q & 31;  q >>= 5;
    const int mt8  = q & 7;   q >>= 3;
    const int kk   = q & 3;   q >>= 2;
    const int kc   = q & 31;  q >>= 5;
    const int mblk = q;       // 128-row block id
    const int s0 = slot ^ kk;
    const int rlow = s0 >> 2, u = s0 & 3;
    const int r0 = mt8 * 16 + rlow;
    const int row0 = mblk * 128 + r0;
    const int clo = kc * 32 + kk * 8 + u;
    auto rd = [&](int row, int col) -> float {
        return (col < 64) ? xf[(size_t)row * 64 + col] : he[(size_t)row * 960 + (col - 64)];
    };
    uint4 o;
    o.x = f2tf32(rd(row0,     clo));
    o.y = f2tf32(rd(row0 + 8, clo));
    o.z = f2tf32(rd(row0,     clo + 4));
    o.w = f2tf32(rd(row0 + 8, clo + 4));
    *reinterpret_cast<uint4*>(g_Afrag + 4 * g) = o;
}

// ================= fused main kernel (TM=64, 2 CTAs/SM, pair-split over n1) =================
__global__ void __launch_bounds__(NTHR, 2)
fused_kernel(const float* __restrict__ b1, const float* __restrict__ bs,
             const float* __restrict__ bi, float* __restrict__ out) {
    extern __shared__ float sm[];
    const uint32_t smb = smem_u32(sm);
    const int tid = threadIdx.x, lane = tid & 31, wid = tid >> 5;
    const int wm = wid & 1, wn = wid >> 1;   // 2x4 warp grid, 32x32 tiles
    const int bid  = blockIdx.x;
    const int mblk = bid >> 1;               // 64-row slab id (0..1023)
    const int half = bid & 1;                // n1 half
    const int m0 = mblk * TM;
    const int h4 = (mblk & 1) * 4;           // which mt8-half of the 128-row A block

    float acc1[2][4][4];
    float acc2[2][4][4];
#pragma unroll
    for (int a = 0; a < 2; ++a)
#pragma unroll
        for (int b = 0; b < 4; ++b)
#pragma unroll
            for (int c = 0; c < 4; ++c) acc2[a][b][c] = 0.f;

    // stage iteration sp into ring slot sp%3
    auto fetch = [&](int sp) {
        const int n1p = half * NN1H + sp / NIT, posp = sp % NIT;
        const int slot = sp % 3;
        const float* wsrc = (posp < NKC)
            ? g_W1frag + ((size_t)(n1p * NKC + posp) << 12)
            : g_W2frag + ((size_t)(n1p * NSC + (posp - NKC)) << 12);
        const uint32_t wdst = smb + (uint32_t)((SM_WB + slot * WSZ + tid * 4) << 2);
#pragma unroll
        for (int i = 0; i < 4; ++i) cp16(wdst + i * 4096, wsrc + tid * 4 + i * 1024);
        if (posp < NKC) {
            const float* asrc = g_Afrag + (((size_t)(mblk >> 1) * NKC + posp) << 12);
#pragma unroll
            for (int i = 0; i < 2; ++i) {
                const int idx = tid + i * 256;        // float4 units, 512 total
                const int kk = idx >> 7, within = idx & 127;
                const float* src = asrc + (size_t)(kk * 8 + h4) * 128 + within * 4;
                const uint32_t dst = smb + (uint32_t)((SM_AB + slot * ASZ + kk * 512 + within * 4) << 2);
                cp16(dst, src);
            }
        }
    };

    // prologue: 2 stages in flight (ring 3, distance 2)
    fetch(0); cp_commit();
    fetch(1); cp_commit();

    for (int s = 0; s < S_H; ++s) {
        cp_wait1();
        __syncthreads();

        const int sp = s + 2;
        if (sp < S_H) fetch(sp);
        cp_commit();

        const int n1l = s / NIT, pos = s % NIT;
        const int n1g = half * NN1H + n1l;
        const int slot = s % 3;
        if (pos < NKC) {
            if (pos == 0) {
#pragma unroll
                for (int a = 0; a < 2; ++a)
#pragma unroll
                    for (int b = 0; b < 4; ++b)
#pragma unroll
                        for (int c = 0; c < 4; ++c) acc1[a][b][c] = 0.f;
            }
            mma_chunk(sm + SM_AB + slot * ASZ, 0, true,
                      sm + SM_WB + slot * WSZ, wm, wn, lane, acc1);
            if (pos == NKC - 1) {
                // epilogue1: q = tf32(relu(acc1 + b1)) -> SMEM in A-fragment layout (mt-dim 4)
                const float* b1p = b1 + n1g * 128 + wn * 32;
                const int g = lane >> 2, t = lane & 3;
#pragma unroll
                for (int nt = 0; nt < 4; ++nt) {
                    const float2 bv = *reinterpret_cast<const float2*>(b1p + nt * 8 + t * 2);
                    const int kk2 = wn * 4 + nt;
#pragma unroll
                    for (int mt = 0; mt < 2; ++mt) {
                        const int mtq = wm * 2 + mt;
#pragma unroll
                        for (int cr = 0; cr < 4; ++cr) {
                            const int e = cr & 1, r0 = cr >> 1;
                            float x = acc1[mt][nt][cr] + (e ? bv.y : bv.x);
                            x = fmaxf(x, 0.f);
                            const int c8 = 2 * t + e;
                            const int qslot = g * 4 + (c8 & 3);
                            const int regp = r0 + 2 * (c8 >> 2);
                            sm[SM_Q + ((kk2 * 4 + mtq) * 32 + qslot) * 4 + regp] =
                                __uint_as_float(f2tf32(x));
                        }
                    }
                }
            }
        } else {
            mma_chunk(sm + SM_Q, (pos - NKC) * 4, false,
                      sm + SM_WB + slot * WSZ, wm, wn, lane, acc2);
        }
    }
    cp_wait0();

    // ---- pair reduction: store partial acc2, second arriver finishes ----
    {
        float* wp = g_part + ((size_t)bid * NTHR + tid) * 32;
#pragma unroll
        for (int mt = 0; mt < 2; ++mt)
#pragma unroll
            for (int nt = 0; nt < 4; ++nt) {
                float4 v;
                v.x = acc2[mt][nt][0]; v.y = acc2[mt][nt][1];
                v.z = acc2[mt][nt][2]; v.w = acc2[mt][nt][3];
                *reinterpret_cast<float4*>(wp + (mt * 4 + nt) * 4) = v;
            }
        __threadfence();
        __syncthreads();
        if (tid == 0) {
            unsigned old = atomicAdd(&g_cnt[mblk], 1u);
            *reinterpret_cast<unsigned*>(&sm[SM_Q]) = old;
        }
        __syncthreads();
        const unsigned old = *reinterpret_cast<const unsigned*>(&sm[SM_Q]);
        if (old == 0u) return;   // first arriver: partner finishes
        __threadfence();
        const float* pp = g_part + ((size_t)(bid ^ 1) * NTHR + tid) * 32;
#pragma unroll
        for (int mt = 0; mt < 2; ++mt)
#pragma unroll
            for (int nt = 0; nt < 4; ++nt) {
                const float4 v = *reinterpret_cast<const float4*>(pp + (mt * 4 + nt) * 4);
                acc2[mt][nt][0] += v.x; acc2[mt][nt][1] += v.y;
                acc2[mt][nt][2] += v.z; acc2[mt][nt][3] += v.w;
            }
    }

    // ---- final epilogue (finisher only): acc2 -> (tanh(x+bs) | x+bi) ----
    {
        const int g = lane >> 2, t = lane & 3;
        const int seg = wn >> 1;                 // 0: slope, 1: intercept
        const int cb  = (wn & 1) * 32;
        const float* bvecs = seg ? bi : bs;
        float* obase = out + (seg ? (size_t)B_ROWS * 64 : 0);
#pragma unroll
        for (int nt = 0; nt < 4; ++nt) {
            const int Cl = cb + nt * 8 + t * 2;
            const float2 bv = *reinterpret_cast<const float2*>(bvecs + Cl);
#pragma unroll
            for (int mt = 0; mt < 2; ++mt) {
#pragma unroll
                for (int rp = 0; rp < 2; ++rp) {
                    const int R = wm * 32 + mt * 16 + g + rp * 8;   // 0..63
                    float x0 = acc2[mt][nt][rp * 2 + 0] + bv.x;
                    float x1 = acc2[mt][nt][rp * 2 + 1] + bv.y;
                    if (seg == 0) { x0 = fast_tanh(x0); x1 = fast_tanh(x1); }
                    float2 o; o.x = x0; o.y = x1;
                    *reinterpret_cast<float2*>(obase + (size_t)(m0 + R) * 64 + Cl) = o;
                }
            }
        }
    }
    __syncthreads();
    if (tid == 0) g_cnt[mblk] = 0u;
}

// ================= launch =================
extern "C" void kernel_launch(void* const* d_in, const int* in_sizes, int n_in,
                              void* d_out, int out_size) {
    const float* xf = (const float*)d_in[0];
    const float* he = (const float*)d_in[1];
    const float* W1 = (const float*)d_in[2];
    const float* b1 = (const float*)d_in[3];
    const float* Ws = (const float*)d_in[4];
    const float* bs = (const float*)d_in[5];
    const float* Wi = (const float*)d_in[6];
    const float* bi = (const float*)d_in[7];
    float* out = (float*)d_out;

    static bool attr_set = false;
    if (!attr_set) {
        cudaFuncSetAttribute(fused_kernel, cudaFuncAttributeMaxDynamicSharedMemorySize, SMEM_BYTES);
        attr_set = true;
    }

    const int prep_w_total = NN1 * NKC * 4096 + NN1 * NSC * 4096;
    prep_w_kernel<<<(prep_w_total + 255) / 256, 256>>>(W1, Ws, Wi);
    const size_t prep_a_blocks = ((size_t)MBLK128 * NKC * 4096 / 4) / 256;
    prep_a_kernel<<<(unsigned)prep_a_blocks, 256>>>(xf, he);
    fused_kernel<<<GRID, NTHR, SMEM_BYTES>>>(b1, bs, bi, out);
}